// round 3
// baseline (speedup 1.0000x reference)
#include <cuda_runtime.h>

#define Bn 8
#define Qn 128
#define Kn 1024
#define Dn 256
#define Hn 256

// -------- scratch (no allocations allowed) --------
__device__ float g_WqT[Dn * Hn];
__device__ float g_WkT[Dn * Hn];
__device__ float g_qproj[Bn * Qn * Hn];
__device__ float g_kproj[Bn * Kn * Hn];
__device__ int   g_valid[Bn];

// ============================================================
// Kernel 0: transpose W_q/W_k to [D][H] layout + decode valid_lens
// (valid_lens declared jnp.int64 in reference; depending on x64 config the
//  buffer may physically be int32 — sniff at runtime: int64 interpretation is
//  chosen iff all 8 values land in [0, K].)
// ============================================================
__global__ void prep_kernel(const float* __restrict__ Wq,
                            const float* __restrict__ Wk,
                            const void*  __restrict__ vlens) {
    int idx = blockIdx.x * blockDim.x + threadIdx.x;
    int stride = gridDim.x * blockDim.x;
    for (int i = idx; i < Dn * Hn; i += stride) {
        int d = i >> 8;          // i / Hn
        int h = i & 255;         // i % Hn
        g_WqT[i] = Wq[h * Dn + d];
        g_WkT[i] = Wk[h * Dn + d];
    }
    if (blockIdx.x == 0 && threadIdx.x == 0) {
        const long long* p64 = (const long long*)vlens;
        const int*       p32 = (const int*)vlens;
        bool ok64 = true;
        for (int i = 0; i < Bn; i++) {
            long long v = p64[i];
            if (v < 0 || v > (long long)Kn) ok64 = false;
        }
        for (int i = 0; i < Bn; i++)
            g_valid[i] = ok64 ? (int)p64[i] : p32[i];
    }
}

// ============================================================
// Kernel 1: projections. Rows 0..1023 = queries->g_qproj (W_q),
// rows 1024..9215 = keys->g_kproj (W_k). Block = 256 threads covers
// 32 rows x 256 h; thread owns 2 h x 16 rows (32 accumulators).
// grid = 9216/32 = 288.
// ============================================================
__global__ __launch_bounds__(256) void proj_kernel(
        const float* __restrict__ queries,
        const float* __restrict__ keys) {
    __shared__ float s_in[32][Dn];   // 32 KB

    int row0 = blockIdx.x * 32;
    bool is_q = (row0 < Bn * Qn);
    const float* in  = is_q ? (queries + (size_t)row0 * Dn)
                            : (keys + (size_t)(row0 - Bn * Qn) * Dn);
    float* out       = is_q ? (g_qproj + (size_t)row0 * Hn)
                            : (g_kproj + (size_t)(row0 - Bn * Qn) * Hn);
    const float* WT  = is_q ? g_WqT : g_WkT;

    // cooperative load of 32 input rows (8192 floats) via float4
    {
        const float4* in4 = (const float4*)in;
        float4* s4 = (float4*)&s_in[0][0];
        #pragma unroll
        for (int i = 0; i < 8; i++)
            s4[threadIdx.x + i * 256] = in4[threadIdx.x + i * 256];
    }
    __syncthreads();

    int hp = (threadIdx.x & 127) * 2;     // h pair
    int rg = (threadIdx.x >> 7) * 16;     // row group base

    float acc0[16], acc1[16];
    #pragma unroll
    for (int r = 0; r < 16; r++) { acc0[r] = 0.f; acc1[r] = 0.f; }

    #pragma unroll 4
    for (int d = 0; d < Dn; d++) {
        float2 w = *(const float2*)(WT + d * Hn + hp);   // coalesced
        #pragma unroll
        for (int r = 0; r < 16; r++) {
            float a = s_in[rg + r][d];                   // broadcast
            acc0[r] = fmaf(a, w.x, acc0[r]);
            acc1[r] = fmaf(a, w.y, acc1[r]);
        }
    }
    #pragma unroll
    for (int r = 0; r < 16; r++)
        *(float2*)(out + (size_t)(rg + r) * Hn + hp) = make_float2(acc0[r], acc1[r]);
}

// ============================================================
// Kernel 2: fused scores + masked softmax + attn@V.
// grid = B*16 = 128 blocks; block = 512 threads (16 warps).
// Each block: one batch b, 8 consecutive q rows.
// Phase A: scores[q][k] = sum_h w_v[h]*tanh(qproj[h]+kproj[k][h]), mask k>=L.
//   warp w -> q = w%8; k staged 8 rows/iter in smem; q-row & w_v in registers.
// Phase B: softmax over K per q row (2 warps per row).
// Phase C: out[q][d] = sum_k attn[q][k]*V[k][d]; 2 k-halves combined in smem.
// ============================================================
__global__ __launch_bounds__(512) void attn_kernel(
        const float* __restrict__ values,
        const float* __restrict__ w_v,
        float* __restrict__ out) {
    __shared__ float s_scores[8][Kn];   // 32 KB
    __shared__ float s_k[8][Hn];        // 8 KB (reused as partial buffer)
    __shared__ float s_red[16];

    int b  = blockIdx.x >> 4;
    int q0 = (blockIdx.x & 15) * 8;
    int tid = threadIdx.x;
    int w = tid >> 5, l = tid & 31;
    int q = w & 7;
    int L = g_valid[b];

    // per-warp register preload: q row and w_v (layout h = l + 32*j)
    float qv[8], wv[8];
    {
        const float* qrow = g_qproj + (size_t)(b * Qn + q0 + q) * Hn;
        #pragma unroll
        for (int j = 0; j < 8; j++) {
            qv[j] = qrow[l + 32 * j];
            wv[j] = w_v[l + 32 * j];
        }
    }

    // ---------------- Phase A: scores ----------------
    const float* kbase = g_kproj + (size_t)b * Kn * Hn;
    int slot0 = w >> 3;   // 0 or 1
    for (int s = 0; s < Kn / 8; s++) {
        int k0 = s * 8;
        __syncthreads();   // previous stage fully consumed
        // cooperative load: 8 contiguous k-rows = 8 KB = 512 float4
        ((float4*)&s_k[0][0])[tid] = ((const float4*)(kbase + (size_t)k0 * Hn))[tid];
        __syncthreads();
        #pragma unroll
        for (int ss = 0; ss < 4; ss++) {
            int slot = slot0 + ss * 2;
            float sum = 0.f;
            #pragma unroll
            for (int j = 0; j < 8; j++) {
                float x = qv[j] + s_k[slot][l + 32 * j];
                float t;
                asm("tanh.approx.f32 %0, %1;" : "=f"(t) : "f"(x));
                sum = fmaf(wv[j], t, sum);
            }
            #pragma unroll
            for (int off = 16; off > 0; off >>= 1)
                sum += __shfl_xor_sync(0xffffffffu, sum, off);
            if (l == 0) {
                int kk = k0 + slot;
                s_scores[q][kk] = (kk < L) ? sum : -1e9f;
            }
        }
    }
    __syncthreads();

    // ---------------- Phase B: softmax per q row ----------------
    {
        int half = w >> 3;
        int base = half * 512;
        float m = -3.4e38f;
        #pragma unroll
        for (int i = 0; i < 16; i++)
            m = fmaxf(m, s_scores[q][base + l + 32 * i]);
        #pragma unroll
        for (int off = 16; off > 0; off >>= 1)
            m = fmaxf(m, __shfl_xor_sync(0xffffffffu, m, off));
        if (l == 0) s_red[w] = m;
        __syncthreads();
        m = fmaxf(s_red[q], s_red[q + 8]);

        float sum = 0.f;
        #pragma unroll
        for (int i = 0; i < 16; i++) {
            int kk = base + l + 32 * i;
            float e = __expf(s_scores[q][kk] - m);
            s_scores[q][kk] = e;
            sum += e;
        }
        #pragma unroll
        for (int off = 16; off > 0; off >>= 1)
            sum += __shfl_xor_sync(0xffffffffu, sum, off);
        __syncthreads();              // everyone done reading maxes
        if (l == 0) s_red[w] = sum;
        __syncthreads();
        float inv = 1.f / (s_red[q] + s_red[q + 8]);
        #pragma unroll
        for (int i = 0; i < 16; i++)
            s_scores[q][base + l + 32 * i] *= inv;
    }
    __syncthreads();

    // ---------------- Phase C: out = attn @ V ----------------
    {
        int d    = tid & 255;
        int half = tid >> 8;          // 2 k-halves of 512
        const float* vb = values + (size_t)b * Kn * Dn;
        float acc[8];
        #pragma unroll
        for (int qq = 0; qq < 8; qq++) acc[qq] = 0.f;

        int kbeg = half * 512;
        for (int k = kbeg; k < kbeg + 512; k++) {
            float v = vb[(size_t)k * Dn + d];            // coalesced, L2-hit
            #pragma unroll
            for (int qq = 0; qq < 8; qq++)
                acc[qq] = fmaf(s_scores[qq][k], v, acc[qq]);  // smem broadcast
        }

        float* part = &s_k[0][0];     // s_k dead -> reuse as 8x256 partials
        if (half == 0) {
            #pragma unroll
            for (int qq = 0; qq < 8; qq++) part[qq * 256 + d] = acc[qq];
        }
        __syncthreads();
        if (half == 1) {
            #pragma unroll
            for (int qq = 0; qq < 8; qq++)
                out[(size_t)(b * Qn + q0 + qq) * Dn + d] = part[qq * 256 + d] + acc[qq];
        }
    }
}

// ============================================================
extern "C" void kernel_launch(void* const* d_in, const int* in_sizes, int n_in,
                              void* d_out, int out_size) {
    const float* queries = (const float*)d_in[0];
    const float* keys    = (const float*)d_in[1];
    const float* values  = (const float*)d_in[2];
    const float* Wq      = (const float*)d_in[3];
    const float* Wk      = (const float*)d_in[4];
    const float* wv      = (const float*)d_in[5];
    const void*  vlens   =               d_in[6];
    float* out = (float*)d_out;

    prep_kernel<<<64, 256>>>(Wq, Wk, vlens);
    proj_kernel<<<(Bn * Qn + Bn * Kn) / 32, 256>>>(queries, keys);
    attn_kernel<<<Bn * (Qn / 8), 512>>>(values, wv, out);
}

// round 4
// speedup vs baseline: 2.4564x; 2.4564x over previous
#include <cuda_runtime.h>

#define Bn 8
#define Qn 128
#define Kn 1024
#define Dn 256
#define Hn 256

// -------- scratch (no allocations allowed) --------
__device__ float g_WqT[Dn * Hn];
__device__ float g_WkT[Dn * Hn];
__device__ float g_qproj[Bn * Qn * Hn];
__device__ float g_kproj[Bn * Kn * Hn];
__device__ float g_scores[Bn * Qn * Kn];   // 4 MB
__device__ int   g_valid[Bn];

// ============================================================
// Kernel 0: tiled transpose of W_q/W_k to [D][H] + valid_lens decode.
// grid = 128 (64 tiles x 2 matrices), block = 256.
// ============================================================
__global__ __launch_bounds__(256) void prep_kernel(const float* __restrict__ Wq,
                                                   const float* __restrict__ Wk,
                                                   const void*  __restrict__ vlens) {
    __shared__ float tile[32][33];
    int m  = blockIdx.x & 1;
    int t  = blockIdx.x >> 1;          // 0..63
    int d0 = (t & 7) * 32;
    int h0 = (t >> 3) * 32;
    const float* src = m ? Wk : Wq;    // [H][D]
    float*       dst = m ? g_WkT : g_WqT;  // [D][H]
    int lx = threadIdx.x & 31, ly = threadIdx.x >> 5;

    #pragma unroll
    for (int i = 0; i < 32; i += 8)
        tile[ly + i][lx] = src[(size_t)(h0 + ly + i) * Dn + d0 + lx];
    __syncthreads();
    #pragma unroll
    for (int i = 0; i < 32; i += 8)
        dst[(size_t)(d0 + ly + i) * Hn + h0 + lx] = tile[lx][ly + i];

    if (blockIdx.x == 0 && threadIdx.x == 0) {
        const long long* p64 = (const long long*)vlens;
        const int*       p32 = (const int*)vlens;
        bool ok64 = true;
        for (int i = 0; i < Bn; i++) {
            long long v = p64[i];
            if (v < 0 || v > (long long)Kn) ok64 = false;
        }
        for (int i = 0; i < Bn; i++)
            g_valid[i] = ok64 ? (int)p64[i] : p32[i];
    }
}

// ============================================================
// Kernel 1: projections. Rows 0..1023 -> g_qproj, 1024..9215 -> g_kproj.
// Block covers 32 rows x 256 h; thread owns 4 consecutive h x 8 rows.
// k-blocks whose 32 rows are all >= valid_len exit early.
// grid = 288, block = 256.
// ============================================================
__global__ __launch_bounds__(256) void proj_kernel(
        const float* __restrict__ queries,
        const float* __restrict__ keys) {
    __shared__ float s_in[32][Dn];     // 32 KB

    int row0 = blockIdx.x * 32;
    bool is_q = (row0 < Bn * Qn);
    if (!is_q) {
        int rel = row0 - Bn * Qn;
        int b   = rel >> 10;
        int kr0 = rel & (Kn - 1);
        if (kr0 >= g_valid[b]) return;   // whole block masked
    }
    const float* in  = is_q ? (queries + (size_t)row0 * Dn)
                            : (keys + (size_t)(row0 - Bn * Qn) * Dn);
    float* out       = is_q ? (g_qproj + (size_t)row0 * Hn)
                            : (g_kproj + (size_t)(row0 - Bn * Qn) * Hn);
    const float* WT  = is_q ? g_WqT : g_WkT;

    {   // cooperative load of 32 input rows (float4)
        const float4* in4 = (const float4*)in;
        float4* s4 = (float4*)&s_in[0][0];
        #pragma unroll
        for (int i = 0; i < 8; i++)
            s4[threadIdx.x + i * 256] = in4[threadIdx.x + i * 256];
    }
    __syncthreads();

    int hq = threadIdx.x & 63;     // h quad (4 h)
    int rg = threadIdx.x >> 6;     // row group (8 rows)

    float acc[8][4];
    #pragma unroll
    for (int r = 0; r < 8; r++)
        #pragma unroll
        for (int j = 0; j < 4; j++) acc[r][j] = 0.f;

    const float4* wt4 = (const float4*)WT;   // [d][64 quads]
    #pragma unroll 2
    for (int d4 = 0; d4 < 64; d4++) {
        float4 w[4];
        #pragma unroll
        for (int j = 0; j < 4; j++)
            w[j] = wt4[(size_t)(d4 * 4 + j) * 64 + hq];   // coalesced LDG.128
        #pragma unroll
        for (int r = 0; r < 8; r++) {
            float4 a = *(const float4*)&s_in[rg * 8 + r][d4 * 4];  // broadcast LDS.128
            #pragma unroll
            for (int j = 0; j < 4; j++) {
                float av = (&a.x)[j];
                acc[r][0] = fmaf(av, w[j].x, acc[r][0]);
                acc[r][1] = fmaf(av, w[j].y, acc[r][1]);
                acc[r][2] = fmaf(av, w[j].z, acc[r][2]);
                acc[r][3] = fmaf(av, w[j].w, acc[r][3]);
            }
        }
    }
    #pragma unroll
    for (int r = 0; r < 8; r++)
        *(float4*)&out[(size_t)(rg * 8 + r) * Hn + hq * 4] =
            make_float4(acc[r][0], acc[r][1], acc[r][2], acc[r][3]);
}

// ============================================================
// Kernel 2: scores. grid = B*16*32 = 4096 small blocks (b, qtile, k-chunk of 32).
// Early-exit when chunk fully masked -> load-balanced MUFU saturation.
// Lane-per-k layout via padded smem transpose: no shuffles; score lands in lane.
// block = 256 (8 warps = 8 q rows).
// ============================================================
__global__ __launch_bounds__(256, 4) void score_kernel(const float* __restrict__ w_v) {
    __shared__ float s_kT[Hn * 33];    // [h][32 k + pad] 33.8 KB
    __shared__ float s_q[8 * Hn];      // 8 KB
    __shared__ float s_wv[Hn];         // 1 KB

    int kc = blockIdx.x & 31;
    int qt = (blockIdx.x >> 5) & 15;
    int b  = blockIdx.x >> 9;
    int L  = g_valid[b];
    int k0 = kc * 32;
    if (k0 >= L) return;               // uniform over block

    int t = threadIdx.x, w = t >> 5, l = t & 31;

    {   // transpose 32 k-rows into s_kT (conflict-free: stride 33 == 1 mod 32)
        int kr = t >> 3, hoct = t & 7;
        const float4* src = (const float4*)(g_kproj + ((size_t)b * Kn + k0 + kr) * Hn);
        #pragma unroll
        for (int i = 0; i < 8; i++) {
            float4 v = src[hoct + i * 8];
            int h = (hoct + i * 8) * 4;
            s_kT[(h + 0) * 33 + kr] = v.x;
            s_kT[(h + 1) * 33 + kr] = v.y;
            s_kT[(h + 2) * 33 + kr] = v.z;
            s_kT[(h + 3) * 33 + kr] = v.w;
        }
    }
    {   // q tile: 8 rows x 256 = 512 float4
        const float4* src = (const float4*)(g_qproj + ((size_t)b * Qn + qt * 8) * Hn);
        float4* dst = (float4*)s_q;
        dst[t]       = src[t];
        dst[t + 256] = src[t + 256];
    }
    if (t < 64) ((float4*)s_wv)[t] = ((const float4*)w_v)[t];
    __syncthreads();

    // warp w = q row; lane l = k within chunk
    float a0 = 0.f, a1 = 0.f, a2 = 0.f, a3 = 0.f;
    const float4* q4  = (const float4*)(s_q + w * Hn);
    const float4* wv4 = (const float4*)s_wv;
    #pragma unroll 4
    for (int h4 = 0; h4 < 64; h4++) {
        float4 qv = q4[h4];            // broadcast LDS.128
        float4 wv = wv4[h4];           // broadcast LDS.128
        int hb = h4 * 4;
        float x0 = qv.x + s_kT[(hb + 0) * 33 + l];
        float x1 = qv.y + s_kT[(hb + 1) * 33 + l];
        float x2 = qv.z + s_kT[(hb + 2) * 33 + l];
        float x3 = qv.w + s_kT[(hb + 3) * 33 + l];
        float t0, t1, t2, t3;
        asm("tanh.approx.f32 %0, %1;" : "=f"(t0) : "f"(x0));
        asm("tanh.approx.f32 %0, %1;" : "=f"(t1) : "f"(x1));
        asm("tanh.approx.f32 %0, %1;" : "=f"(t2) : "f"(x2));
        asm("tanh.approx.f32 %0, %1;" : "=f"(t3) : "f"(x3));
        a0 = fmaf(wv.x, t0, a0);
        a1 = fmaf(wv.y, t1, a1);
        a2 = fmaf(wv.z, t2, a2);
        a3 = fmaf(wv.w, t3, a3);
    }
    float s = (a0 + a1) + (a2 + a3);
    int kk = k0 + l;
    if (kk < L)
        g_scores[((size_t)b * Qn + qt * 8 + w) * Kn + kk] = s;   // coalesced STG
}

// ============================================================
// Kernel 3: masked softmax + attn @ V. grid = 128 (b, qtile), block = 512.
// Softmax: warp (q, k-half) holds its 512 scores in registers (1 global read).
// AV: thread owns one d, half the valid k range; float4 broadcast attn loads.
// ============================================================
__global__ __launch_bounds__(512) void softAV_kernel(
        const float* __restrict__ values,
        float* __restrict__ out) {
    __shared__ float s_attn[8 * Kn];   // 32 KB
    __shared__ float s_part[8 * 256];  // 8 KB
    __shared__ float s_red[32];

    int b  = blockIdx.x >> 4;
    int qt = blockIdx.x & 15;
    int L  = g_valid[b];
    int t  = threadIdx.x, w = t >> 5, l = t & 31;
    int qB = w & 7, hB = w >> 3;

    // ---- softmax ----
    const float* gs = g_scores + ((size_t)b * Qn + qt * 8 + qB) * Kn;
    int base = hB * 512;
    float vals[16];
    float m = -3.4e38f;
    #pragma unroll
    for (int i = 0; i < 16; i++) {
        int kk = base + l + 32 * i;
        float v = (kk < L) ? gs[kk] : -1e9f;
        vals[i] = v;
        m = fmaxf(m, v);
    }
    #pragma unroll
    for (int o = 16; o > 0; o >>= 1)
        m = fmaxf(m, __shfl_xor_sync(0xffffffffu, m, o));
    if (l == 0) s_red[w] = m;
    __syncthreads();
    m = fmaxf(s_red[qB], s_red[qB + 8]);

    float sum = 0.f;
    #pragma unroll
    for (int i = 0; i < 16; i++) {
        float e = __expf(vals[i] - m);
        vals[i] = e;
        sum += e;
    }
    #pragma unroll
    for (int o = 16; o > 0; o >>= 1)
        sum += __shfl_xor_sync(0xffffffffu, sum, o);
    if (l == 0) s_red[16 + w] = sum;
    __syncthreads();
    float inv = 1.f / (s_red[16 + qB] + s_red[24 + qB]);
    #pragma unroll
    for (int i = 0; i < 16; i++)
        s_attn[qB * Kn + base + l + 32 * i] = vals[i] * inv;
    __syncthreads();

    // ---- attn @ V (skip masked k: weights there are exactly 0) ----
    int d    = t & 255;
    int half = t >> 8;
    int kLim = (L == 0) ? Kn : ((L + 3) & ~3);
    int mid  = ((kLim >> 1) + 3) & ~3;
    int kb   = half ? mid : 0;
    int ke   = half ? kLim : mid;
    const float* vb = values + (size_t)b * Kn * Dn;

    float acc[8];
    #pragma unroll
    for (int qq = 0; qq < 8; qq++) acc[qq] = 0.f;

    for (int k = kb; k < ke; k += 4) {
        float v0 = vb[(size_t)(k + 0) * Dn + d];
        float v1 = vb[(size_t)(k + 1) * Dn + d];
        float v2 = vb[(size_t)(k + 2) * Dn + d];
        float v3 = vb[(size_t)(k + 3) * Dn + d];
        #pragma unroll
        for (int qq = 0; qq < 8; qq++) {
            float4 a = *(const float4*)&s_attn[qq * Kn + k];   // broadcast LDS.128
            acc[qq] = fmaf(a.x, v0, acc[qq]);
            acc[qq] = fmaf(a.y, v1, acc[qq]);
            acc[qq] = fmaf(a.z, v2, acc[qq]);
            acc[qq] = fmaf(a.w, v3, acc[qq]);
        }
    }

    if (half == 0) {
        #pragma unroll
        for (int qq = 0; qq < 8; qq++) s_part[qq * 256 + d] = acc[qq];
    }
    __syncthreads();
    if (half == 1) {
        #pragma unroll
        for (int qq = 0; qq < 8; qq++)
            out[((size_t)b * Qn + qt * 8 + qq) * Dn + d] = s_part[qq * 256 + d] + acc[qq];
    }
}

// ============================================================
extern "C" void kernel_launch(void* const* d_in, const int* in_sizes, int n_in,
                              void* d_out, int out_size) {
    const float* queries = (const float*)d_in[0];
    const float* keys    = (const float*)d_in[1];
    const float* values  = (const float*)d_in[2];
    const float* Wq      = (const float*)d_in[3];
    const float* Wk      = (const float*)d_in[4];
    const float* wv      = (const float*)d_in[5];
    const void*  vlens   =               d_in[6];
    float* out = (float*)d_out;

    prep_kernel<<<128, 256>>>(Wq, Wk, vlens);
    proj_kernel<<<(Bn * Qn + Bn * Kn) / 32, 256>>>(queries, keys);
    score_kernel<<<Bn * 16 * 32, 256>>>(wv);
    softAV_kernel<<<Bn * 16, 512>>>(values, out);
}

// round 6
// speedup vs baseline: 2.9145x; 1.1865x over previous
#include <cuda_runtime.h>

#define Bn 8
#define Qn 128
#define Kn 1024
#define Dn 256
#define Hn 256

// -------- scratch (no allocations allowed) --------
__device__ float g_WqT[Dn * Hn];
__device__ float g_WkT[Dn * Hn];
__device__ float g_qproj[Bn * Qn * Hn];
__device__ float g_kproj[Bn * Kn * Hn];
__device__ float g_scores[Bn * Qn * Kn];   // 4 MB; after softmax holds attn weights
__device__ int   g_valid[Bn];

// ============================================================
// Kernel 0: tiled transpose of W_q/W_k to [D][H] + valid_lens decode.
// grid = 128 (64 tiles x 2 matrices), block = 256.
// ============================================================
__global__ __launch_bounds__(256) void prep_kernel(const float* __restrict__ Wq,
                                                   const float* __restrict__ Wk,
                                                   const void*  __restrict__ vlens) {
    __shared__ float tile[32][33];
    int m  = blockIdx.x & 1;
    int t  = blockIdx.x >> 1;          // 0..63
    int d0 = (t & 7) * 32;
    int h0 = (t >> 3) * 32;
    const float* src = m ? Wk : Wq;    // [H][D]
    float*       dst = m ? g_WkT : g_WqT;  // [D][H]
    int lx = threadIdx.x & 31, ly = threadIdx.x >> 5;

    #pragma unroll
    for (int i = 0; i < 32; i += 8)
        tile[ly + i][lx] = src[(size_t)(h0 + ly + i) * Dn + d0 + lx];
    __syncthreads();
    #pragma unroll
    for (int i = 0; i < 32; i += 8)
        dst[(size_t)(d0 + ly + i) * Hn + h0 + lx] = tile[lx][ly + i];

    if (blockIdx.x == 0 && threadIdx.x == 0) {
        const long long* p64 = (const long long*)vlens;
        const int*       p32 = (const int*)vlens;
        bool ok64 = true;
        for (int i = 0; i < Bn; i++) {
            long long v = p64[i];
            if (v < 0 || v > (long long)Kn) ok64 = false;
        }
        for (int i = 0; i < Bn; i++)
            g_valid[i] = ok64 ? (int)p64[i] : p32[i];
    }
}

// ============================================================
// Kernel 1: projections. Rows 0..1023 -> g_qproj, 1024..9215 -> g_kproj.
// Block covers 32 rows x 256 h; thread owns 4 consecutive h x 8 rows.
// k-blocks whose 32 rows are all >= valid_len exit early.
// grid = 288, block = 256.
// ============================================================
__global__ __launch_bounds__(256) void proj_kernel(
        const float* __restrict__ queries,
        const float* __restrict__ keys) {
    __shared__ float s_in[32][Dn];     // 32 KB

    int row0 = blockIdx.x * 32;
    bool is_q = (row0 < Bn * Qn);
    if (!is_q) {
        int rel = row0 - Bn * Qn;
        int b   = rel >> 10;
        int kr0 = rel & (Kn - 1);
        if (kr0 >= g_valid[b]) return;   // whole block masked
    }
    const float* in  = is_q ? (queries + (size_t)row0 * Dn)
                            : (keys + (size_t)(row0 - Bn * Qn) * Dn);
    float* out       = is_q ? (g_qproj + (size_t)row0 * Hn)
                            : (g_kproj + (size_t)(row0 - Bn * Qn) * Hn);
    const float* WT  = is_q ? g_WqT : g_WkT;

    {   // cooperative load of 32 input rows (float4)
        const float4* in4 = (const float4*)in;
        float4* s4 = (float4*)&s_in[0][0];
        #pragma unroll
        for (int i = 0; i < 8; i++)
            s4[threadIdx.x + i * 256] = in4[threadIdx.x + i * 256];
    }
    __syncthreads();

    int hq = threadIdx.x & 63;     // h quad (4 h)
    int rg = threadIdx.x >> 6;     // row group (8 rows)

    float acc[8][4];
    #pragma unroll
    for (int r = 0; r < 8; r++)
        #pragma unroll
        for (int j = 0; j < 4; j++) acc[r][j] = 0.f;

    const float4* wt4 = (const float4*)WT;   // [d][64 quads]
    #pragma unroll 2
    for (int d4 = 0; d4 < 64; d4++) {
        float4 w[4];
        #pragma unroll
        for (int j = 0; j < 4; j++)
            w[j] = wt4[(size_t)(d4 * 4 + j) * 64 + hq];   // coalesced LDG.128
        #pragma unroll
        for (int r = 0; r < 8; r++) {
            float4 a = *(const float4*)&s_in[rg * 8 + r][d4 * 4];  // broadcast LDS.128
            #pragma unroll
            for (int j = 0; j < 4; j++) {
                float av = (&a.x)[j];
                acc[r][0] = fmaf(av, w[j].x, acc[r][0]);
                acc[r][1] = fmaf(av, w[j].y, acc[r][1]);
                acc[r][2] = fmaf(av, w[j].z, acc[r][2]);
                acc[r][3] = fmaf(av, w[j].w, acc[r][3]);
            }
        }
    }
    #pragma unroll
    for (int r = 0; r < 8; r++)
        *(float4*)&out[(size_t)(rg * 8 + r) * Hn + hq * 4] =
            make_float4(acc[r][0], acc[r][1], acc[r][2], acc[r][3]);
}

// ============================================================
// Kernel 2: scores. grid = B*16*32 = 4096 small blocks (b, qtile, k-chunk of 32).
// Early-exit when chunk fully masked -> load-balanced MUFU saturation.
// Lane-per-k layout via padded smem transpose: no shuffles.
// block = 256 (8 warps = 8 q rows).
// ============================================================
__global__ __launch_bounds__(256, 4) void score_kernel(const float* __restrict__ w_v) {
    __shared__ float s_kT[Hn * 33];    // [h][32 k + pad]
    __shared__ float s_q[8 * Hn];
    __shared__ float s_wv[Hn];

    int kc = blockIdx.x & 31;
    int qt = (blockIdx.x >> 5) & 15;
    int b  = blockIdx.x >> 9;
    int L  = g_valid[b];
    int k0 = kc * 32;
    if (k0 >= L) return;               // uniform over block

    int t = threadIdx.x, w = t >> 5, l = t & 31;

    {   // transpose 32 k-rows into s_kT (conflict-free: stride 33 == 1 mod 32)
        int kr = t >> 3, hoct = t & 7;
        const float4* src = (const float4*)(g_kproj + ((size_t)b * Kn + k0 + kr) * Hn);
        #pragma unroll
        for (int i = 0; i < 8; i++) {
            float4 v = src[hoct + i * 8];
            int h = (hoct + i * 8) * 4;
            s_kT[(h + 0) * 33 + kr] = v.x;
            s_kT[(h + 1) * 33 + kr] = v.y;
            s_kT[(h + 2) * 33 + kr] = v.z;
            s_kT[(h + 3) * 33 + kr] = v.w;
        }
    }
    {   // q tile: 8 rows x 256 = 512 float4
        const float4* src = (const float4*)(g_qproj + ((size_t)b * Qn + qt * 8) * Hn);
        float4* dst = (float4*)s_q;
        dst[t]       = src[t];
        dst[t + 256] = src[t + 256];
    }
    if (t < 64) ((float4*)s_wv)[t] = ((const float4*)w_v)[t];
    __syncthreads();

    // warp w = q row; lane l = k within chunk
    float a0 = 0.f, a1 = 0.f, a2 = 0.f, a3 = 0.f;
    const float4* q4  = (const float4*)(s_q + w * Hn);
    const float4* wv4 = (const float4*)s_wv;
    #pragma unroll 4
    for (int h4 = 0; h4 < 64; h4++) {
        float4 qv = q4[h4];
        float4 wv = wv4[h4];
        int hb = h4 * 4;
        float x0 = qv.x + s_kT[(hb + 0) * 33 + l];
        float x1 = qv.y + s_kT[(hb + 1) * 33 + l];
        float x2 = qv.z + s_kT[(hb + 2) * 33 + l];
        float x3 = qv.w + s_kT[(hb + 3) * 33 + l];
        float t0, t1, t2, t3;
        asm("tanh.approx.f32 %0, %1;" : "=f"(t0) : "f"(x0));
        asm("tanh.approx.f32 %0, %1;" : "=f"(t1) : "f"(x1));
        asm("tanh.approx.f32 %0, %1;" : "=f"(t2) : "f"(x2));
        asm("tanh.approx.f32 %0, %1;" : "=f"(t3) : "f"(x3));
        a0 = fmaf(wv.x, t0, a0);
        a1 = fmaf(wv.y, t1, a1);
        a2 = fmaf(wv.z, t2, a2);
        a3 = fmaf(wv.w, t3, a3);
    }
    float s = (a0 + a1) + (a2 + a3);
    int kk = k0 + l;
    if (kk < L)
        g_scores[((size_t)b * Qn + qt * 8 + w) * Kn + kk] = s;   // coalesced STG
}

// ============================================================
// Kernel 3: masked softmax in place on g_scores -> attn weights.
// grid = B*Qn/2 = 512 blocks; block = 256 (8 warps, 4 warps per q row).
// Each warp owns a 256-entry quarter of one row in registers.
// Writes the FULL row (zeros beyond valid region); L==0 -> uniform 1/1024.
// ============================================================
__global__ __launch_bounds__(256) void softmax_kernel() {
    __shared__ float s_max[8];
    __shared__ float s_sum[8];

    int t = threadIdx.x, w = t >> 5, l = t & 31;
    int r   = w >> 2;                       // 0/1: row within block
    int row = blockIdx.x * 2 + r;           // global (b*Qn + q)
    int b   = row >> 7;
    int L   = g_valid[b];
    float* gs = g_scores + (size_t)row * Kn;
    int base = (w & 3) * 256;

    float vals[8];
    float m = -3.4e38f;
    #pragma unroll
    for (int i = 0; i < 8; i++) {
        int kk = base + l + 32 * i;
        float v = (kk < L) ? gs[kk] : -1e9f;   // never read unwritten memory
        vals[i] = v;
        m = fmaxf(m, v);
    }
    #pragma unroll
    for (int o = 16; o > 0; o >>= 1)
        m = fmaxf(m, __shfl_xor_sync(0xffffffffu, m, o));
    if (l == 0) s_max[w] = m;
    __syncthreads();
    m = fmaxf(fmaxf(s_max[r * 4 + 0], s_max[r * 4 + 1]),
              fmaxf(s_max[r * 4 + 2], s_max[r * 4 + 3]));

    float sum = 0.f;
    #pragma unroll
    for (int i = 0; i < 8; i++) {
        float e = __expf(vals[i] - m);   // masked -> exp(-1e9-m)=0 (L>0); L==0 -> 1
        vals[i] = e;
        sum += e;
    }
    #pragma unroll
    for (int o = 16; o > 0; o >>= 1)
        sum += __shfl_xor_sync(0xffffffffu, sum, o);
    if (l == 0) s_sum[w] = sum;
    __syncthreads();
    float inv = 1.f / (s_sum[r * 4 + 0] + s_sum[r * 4 + 1] +
                       s_sum[r * 4 + 2] + s_sum[r * 4 + 3]);
    #pragma unroll
    for (int i = 0; i < 8; i++)
        gs[base + l + 32 * i] = vals[i] * inv;   // full row written (zeros when masked)
}

// ============================================================
// Kernel 4: out = attn @ V.
// grid = B*16*4 = 512 blocks (b, qtile, d-chunk of 64); block = 256.
// Thread owns one d and 1/4 of the valid k range; partials combined in smem.
// attn staged in smem once per block; masked k skipped (weights are 0 anyway).
// ============================================================
__global__ __launch_bounds__(256) void av_kernel(
        const float* __restrict__ values,
        float* __restrict__ out) {
    __shared__ float s_attn[8][Kn];       // 32 KB
    __shared__ float s_part[4][8][64];    // 8 KB

    int dc = blockIdx.x & 3;
    int qt = (blockIdx.x >> 2) & 15;
    int b  = blockIdx.x >> 6;
    int L  = g_valid[b];
    int kEff = (L == 0) ? Kn : L;
    int t = threadIdx.x;

    {   // stage 8 attn rows (8 KB each block reads 32 KB coalesced)
        const float4* src = (const float4*)(g_scores + ((size_t)(b * Qn + qt * 8)) * Kn);
        float4* dst = (float4*)&s_attn[0][0];
        #pragma unroll
        for (int i = 0; i < 8; i++)
            dst[t + i * 256] = src[t + i * 256];
    }
    __syncthreads();

    int dl = t & 63;                 // d within chunk
    int ks = t >> 6;                 // k-slice 0..3
    int d  = dc * 64 + dl;
    const float* vb = values + (size_t)b * Kn * Dn + d;

    int kLim = (kEff + 3) & ~3;
    int per  = (((kLim >> 2) + 3) & ~3);       // per-slice span, multiple of 4
    int kb   = ks * per;
    int ke   = min(kb + per, kLim);

    float acc[8];
    #pragma unroll
    for (int qq = 0; qq < 8; qq++) acc[qq] = 0.f;

    for (int k = kb; k < ke; k += 4) {
        float v0 = vb[(size_t)(k + 0) * Dn];
        float v1 = vb[(size_t)(k + 1) * Dn];
        float v2 = vb[(size_t)(k + 2) * Dn];
        float v3 = vb[(size_t)(k + 3) * Dn];
        #pragma unroll
        for (int qq = 0; qq < 8; qq++) {
            float4 a = *(const float4*)&s_attn[qq][k];   // broadcast LDS.128
            acc[qq] = fmaf(a.x, v0, acc[qq]);
            acc[qq] = fmaf(a.y, v1, acc[qq]);
            acc[qq] = fmaf(a.z, v2, acc[qq]);
            acc[qq] = fmaf(a.w, v3, acc[qq]);
        }
    }

    #pragma unroll
    for (int qq = 0; qq < 8; qq++) s_part[ks][qq][dl] = acc[qq];
    __syncthreads();

    for (int idx = t; idx < 512; idx += 256) {
        int qq  = idx >> 6;
        int dl2 = idx & 63;
        float s = s_part[0][qq][dl2] + s_part[1][qq][dl2] +
                  s_part[2][qq][dl2] + s_part[3][qq][dl2];
        out[((size_t)(b * Qn + qt * 8 + qq)) * Dn + dc * 64 + dl2] = s;
    }
}

// ============================================================
extern "C" void kernel_launch(void* const* d_in, const int* in_sizes, int n_in,
                              void* d_out, int out_size) {
    const float* queries = (const float*)d_in[0];
    const float* keys    = (const float*)d_in[1];
    const float* values  = (const float*)d_in[2];
    const float* Wq      = (const float*)d_in[3];
    const float* Wk      = (const float*)d_in[4];
    const float* wv      = (const float*)d_in[5];
    const void*  vlens   =               d_in[6];
    float* out = (float*)d_out;

    prep_kernel<<<128, 256>>>(Wq, Wk, vlens);
    proj_kernel<<<(Bn * Qn + Bn * Kn) / 32, 256>>>(queries, keys);
    score_kernel<<<Bn * 16 * 32, 256>>>(wv);
    softmax_kernel<<<Bn * Qn / 2, 256>>>();
    av_kernel<<<Bn * 16 * 4, 256>>>(values, out);
}

// round 7
// speedup vs baseline: 3.0232x; 1.0373x over previous
#include <cuda_runtime.h>
#include <cuda_fp16.h>

#define Bn 8
#define Qn 128
#define Kn 1024
#define Dn 256
#define Hn 256

// -------- scratch (no allocations allowed) --------
__device__ float  g_WqT[Dn * Hn];
__device__ float  g_WkT[Dn * Hn];
__device__ __half g_qprojH[Bn * Qn * Hn];
__device__ __half g_kprojH[Bn * Kn * Hn];
__device__ __half g_wvH[Hn];
__device__ float  g_scores[Bn * Qn * Kn];   // 4 MB; after softmax holds attn weights
__device__ int    g_valid[Bn];

__device__ __forceinline__ __half2 u2h(unsigned u) { __half2 h; *(unsigned*)&h = u; return h; }

// ============================================================
// Kernel 0: tiled transpose of W_q/W_k to [D][H] + w_v->half + valid decode.
// grid = 128 (64 tiles x 2 matrices), block = 256.
// ============================================================
__global__ __launch_bounds__(256) void prep_kernel(const float* __restrict__ Wq,
                                                   const float* __restrict__ Wk,
                                                   const float* __restrict__ wv,
                                                   const void*  __restrict__ vlens) {
    __shared__ float tile[32][33];
    int m  = blockIdx.x & 1;
    int t  = blockIdx.x >> 1;          // 0..63
    int d0 = (t & 7) * 32;
    int h0 = (t >> 3) * 32;
    const float* src = m ? Wk : Wq;    // [H][D]
    float*       dst = m ? g_WkT : g_WqT;  // [D][H]
    int lx = threadIdx.x & 31, ly = threadIdx.x >> 5;

    #pragma unroll
    for (int i = 0; i < 32; i += 8)
        tile[ly + i][lx] = src[(size_t)(h0 + ly + i) * Dn + d0 + lx];
    __syncthreads();
    #pragma unroll
    for (int i = 0; i < 32; i += 8)
        dst[(size_t)(d0 + ly + i) * Hn + h0 + lx] = tile[lx][ly + i];

    if (blockIdx.x == 1)
        g_wvH[threadIdx.x] = __float2half_rn(wv[threadIdx.x]);

    if (blockIdx.x == 0 && threadIdx.x == 0) {
        const long long* p64 = (const long long*)vlens;
        const int*       p32 = (const int*)vlens;
        bool ok64 = true;
        for (int i = 0; i < Bn; i++) {
            long long v = p64[i];
            if (v < 0 || v > (long long)Kn) ok64 = false;
        }
        for (int i = 0; i < Bn; i++)
            g_valid[i] = ok64 ? (int)p64[i] : p32[i];
    }
}

// ============================================================
// Kernel 1: projections -> HALF outputs (only the score kernel consumes them).
// fp32 FFMA accumulate, rounded to half at store. Masked k-blocks exit early.
// grid = 288, block = 256; thread owns 4 h x 8 rows.
// ============================================================
__global__ __launch_bounds__(256) void proj_kernel(
        const float* __restrict__ queries,
        const float* __restrict__ keys) {
    __shared__ float s_in[32][Dn];     // 32 KB

    int row0 = blockIdx.x * 32;
    bool is_q = (row0 < Bn * Qn);
    if (!is_q) {
        int rel = row0 - Bn * Qn;
        int b   = rel >> 10;
        int kr0 = rel & (Kn - 1);
        if (kr0 >= g_valid[b]) return;   // whole block masked
    }
    const float* in  = is_q ? (queries + (size_t)row0 * Dn)
                            : (keys + (size_t)(row0 - Bn * Qn) * Dn);
    __half* out      = is_q ? (g_qprojH + (size_t)row0 * Hn)
                            : (g_kprojH + (size_t)(row0 - Bn * Qn) * Hn);
    const float* WT  = is_q ? g_WqT : g_WkT;

    {   // cooperative load of 32 input rows (float4)
        const float4* in4 = (const float4*)in;
        float4* s4 = (float4*)&s_in[0][0];
        #pragma unroll
        for (int i = 0; i < 8; i++)
            s4[threadIdx.x + i * 256] = in4[threadIdx.x + i * 256];
    }
    __syncthreads();

    int hq = threadIdx.x & 63;     // h quad (4 h)
    int rg = threadIdx.x >> 6;     // row group (8 rows)

    float acc[8][4];
    #pragma unroll
    for (int r = 0; r < 8; r++)
        #pragma unroll
        for (int j = 0; j < 4; j++) acc[r][j] = 0.f;

    const float4* wt4 = (const float4*)WT;   // [d][64 quads]
    #pragma unroll 2
    for (int d4 = 0; d4 < 64; d4++) {
        float4 w[4];
        #pragma unroll
        for (int j = 0; j < 4; j++)
            w[j] = wt4[(size_t)(d4 * 4 + j) * 64 + hq];   // coalesced LDG.128
        #pragma unroll
        for (int r = 0; r < 8; r++) {
            float4 a = *(const float4*)&s_in[rg * 8 + r][d4 * 4];  // broadcast LDS.128
            #pragma unroll
            for (int j = 0; j < 4; j++) {
                float av = (&a.x)[j];
                acc[r][0] = fmaf(av, w[j].x, acc[r][0]);
                acc[r][1] = fmaf(av, w[j].y, acc[r][1]);
                acc[r][2] = fmaf(av, w[j].z, acc[r][2]);
                acc[r][3] = fmaf(av, w[j].w, acc[r][3]);
            }
        }
    }
    #pragma unroll
    for (int r = 0; r < 8; r++) {
        __half2 h01 = __floats2half2_rn(acc[r][0], acc[r][1]);
        __half2 h23 = __floats2half2_rn(acc[r][2], acc[r][3]);
        uint2 u = make_uint2(*(unsigned*)&h01, *(unsigned*)&h23);
        *(uint2*)&out[(size_t)(rg * 8 + r) * Hn + hq * 4] = u;   // STG.64 coalesced
    }
}

// ============================================================
// Kernel 2: scores via tanh.approx.f16x2 (2 tanh per MUFU issue).
// grid = B*16*32 = 4096 blocks (b, qtile, k-chunk of 32); early-exit masked.
// Lane l = k; 8 warps = 8 q rows. kT staged as half2[h-pair][33 k] transpose.
// Pair products summed in half2, flushed to fp32 every 8 h.
// ============================================================
__global__ __launch_bounds__(256, 6) void score_kernel() {
    __shared__ __half2 s_kT2[128 * 33];   // 16.9 KB  [h2][32 k + pad]
    __shared__ __half2 s_q2[8 * 128];     // 4 KB
    __shared__ __half2 s_wv2[128];        // 0.5 KB

    int kc = blockIdx.x & 31;
    int qt = (blockIdx.x >> 5) & 15;
    int b  = blockIdx.x >> 9;
    int L  = g_valid[b];
    int k0 = kc * 32;
    if (k0 >= L) return;               // uniform over block

    int t = threadIdx.x, w = t >> 5, l = t & 31;

    {   // transpose 32 k-rows (half) into s_kT2; conflict-free STS (stride 33)
        int kr = t >> 3, cg = t & 7;
        const uint4* src = (const uint4*)(g_kprojH + ((size_t)b * Kn + k0 + kr) * Hn);
        #pragma unroll
        for (int i = 0; i < 4; i++) {
            uint4 u = src[cg + i * 8];            // 8 halves = 4 h2
            int h2 = (cg + i * 8) * 4;
            s_kT2[(h2 + 0) * 33 + kr] = u2h(u.x);
            s_kT2[(h2 + 1) * 33 + kr] = u2h(u.y);
            s_kT2[(h2 + 2) * 33 + kr] = u2h(u.z);
            s_kT2[(h2 + 3) * 33 + kr] = u2h(u.w);
        }
    }
    {   // q tile: 8 rows x 512 B = 256 uint4
        const uint4* src = (const uint4*)(g_qprojH + ((size_t)b * Qn + qt * 8) * Hn);
        ((uint4*)s_q2)[t] = src[t];
    }
    if (t < 32) ((uint4*)s_wv2)[t] = ((const uint4*)g_wvH)[t];
    __syncthreads();

    const uint4* q4 = (const uint4*)(s_q2 + (size_t)w * 128);
    const uint4* w4 = (const uint4*)s_wv2;
    float accx = 0.f, accy = 0.f;

    #pragma unroll 8
    for (int i = 0; i < 32; i++) {          // 8 h per iter
        uint4 qu = q4[i];                   // broadcast LDS.128 (4 h2)
        uint4 wu = w4[i];                   // broadcast LDS.128
        const __half2* kp = &s_kT2[(size_t)(i * 4) * 33 + l];
        unsigned x0, x1, x2, x3, t0, t1, t2, t3;
        __half2 h;
        h = __hadd2(u2h(qu.x), kp[0 * 33]); x0 = *(unsigned*)&h;
        h = __hadd2(u2h(qu.y), kp[1 * 33]); x1 = *(unsigned*)&h;
        h = __hadd2(u2h(qu.z), kp[2 * 33]); x2 = *(unsigned*)&h;
        h = __hadd2(u2h(qu.w), kp[3 * 33]); x3 = *(unsigned*)&h;
        asm("tanh.approx.f16x2 %0, %1;" : "=r"(t0) : "r"(x0));
        asm("tanh.approx.f16x2 %0, %1;" : "=r"(t1) : "r"(x1));
        asm("tanh.approx.f16x2 %0, %1;" : "=r"(t2) : "r"(x2));
        asm("tanh.approx.f16x2 %0, %1;" : "=r"(t3) : "r"(x3));
        __half2 p0 = __hmul2(u2h(wu.x), u2h(t0));
        __half2 p1 = __hmul2(u2h(wu.y), u2h(t1));
        __half2 p2 = __hmul2(u2h(wu.z), u2h(t2));
        __half2 p3 = __hmul2(u2h(wu.w), u2h(t3));
        __half2 s = __hadd2(__hadd2(p0, p1), __hadd2(p2, p3));
        float2 f = __half22float2(s);       // flush every 8 h -> fp32
        accx += f.x;
        accy += f.y;
    }
    float s = accx + accy;
    int kk = k0 + l;
    if (kk < L)
        g_scores[((size_t)b * Qn + qt * 8 + w) * Kn + kk] = s;   // coalesced STG
}

// ============================================================
// Kernel 3: masked softmax in place on g_scores (fp32) -> attn weights.
// grid = 512; block = 256 (4 warps per q row). Vectorized float4 I/O.
// Full row written (zeros beyond valid); L==0 -> uniform 1/1024.
// ============================================================
__global__ __launch_bounds__(256) void softmax_kernel() {
    __shared__ float s_max[8];
    __shared__ float s_sum[8];

    int t = threadIdx.x, w = t >> 5, l = t & 31;
    int r   = w >> 2;                       // row within block
    int row = blockIdx.x * 2 + r;           // global (b*Qn + q)
    int b   = row >> 7;
    int L   = g_valid[b];
    float* gs = g_scores + (size_t)row * Kn;
    int base = (w & 3) * 256 + l * 8;       // 8 consecutive per lane

    float4 v0 = *(const float4*)(gs + base);
    float4 v1 = *(const float4*)(gs + base + 4);
    float vals[8] = {v0.x, v0.y, v0.z, v0.w, v1.x, v1.y, v1.z, v1.w};
    float m = -3.4e38f;
    #pragma unroll
    for (int i = 0; i < 8; i++) {
        if (base + i >= L) vals[i] = -1e9f;   // garbage beyond L -> masked
        m = fmaxf(m, vals[i]);
    }
    #pragma unroll
    for (int o = 16; o > 0; o >>= 1)
        m = fmaxf(m, __shfl_xor_sync(0xffffffffu, m, o));
    if (l == 0) s_max[w] = m;
    __syncthreads();
    m = fmaxf(fmaxf(s_max[r * 4 + 0], s_max[r * 4 + 1]),
              fmaxf(s_max[r * 4 + 2], s_max[r * 4 + 3]));

    float sum = 0.f;
    #pragma unroll
    for (int i = 0; i < 8; i++) {
        float e = __expf(vals[i] - m);
        vals[i] = e;
        sum += e;
    }
    #pragma unroll
    for (int o = 16; o > 0; o >>= 1)
        sum += __shfl_xor_sync(0xffffffffu, sum, o);
    if (l == 0) s_sum[w] = sum;
    __syncthreads();
    float inv = 1.f / (s_sum[r * 4 + 0] + s_sum[r * 4 + 1] +
                       s_sum[r * 4 + 2] + s_sum[r * 4 + 3]);
    *(float4*)(gs + base)     = make_float4(vals[0] * inv, vals[1] * inv,
                                            vals[2] * inv, vals[3] * inv);
    *(float4*)(gs + base + 4) = make_float4(vals[4] * inv, vals[5] * inv,
                                            vals[6] * inv, vals[7] * inv);
}

// ============================================================
// Kernel 4: out = attn @ V.
// grid = 512 (b, qtile, d-chunk of 64); block = 256; 4-way k-split in smem.
// ============================================================
__global__ __launch_bounds__(256) void av_kernel(
        const float* __restrict__ values,
        float* __restrict__ out) {
    __shared__ float s_attn[8][Kn];       // 32 KB
    __shared__ float s_part[4][8][64];    // 8 KB

    int dc = blockIdx.x & 3;
    int qt = (blockIdx.x >> 2) & 15;
    int b  = blockIdx.x >> 6;
    int L  = g_valid[b];
    int kEff = (L == 0) ? Kn : L;
    int t = threadIdx.x;

    {   // stage 8 attn rows coalesced
        const float4* src = (const float4*)(g_scores + ((size_t)(b * Qn + qt * 8)) * Kn);
        float4* dst = (float4*)&s_attn[0][0];
        #pragma unroll
        for (int i = 0; i < 8; i++)
            dst[t + i * 256] = src[t + i * 256];
    }
    __syncthreads();

    int dl = t & 63;                 // d within chunk
    int ks = t >> 6;                 // k-slice 0..3
    int d  = dc * 64 + dl;
    const float* vb = values + (size_t)b * Kn * Dn + d;

    int kLim = (kEff + 3) & ~3;
    int per  = (((kLim >> 2) + 3) & ~3);       // per-slice span, multiple of 4
    int kb   = ks * per;
    int ke   = min(kb + per, kLim);

    float acc[8];
    #pragma unroll
    for (int qq = 0; qq < 8; qq++) acc[qq] = 0.f;

    for (int k = kb; k < ke; k += 4) {
        float v0 = vb[(size_t)(k + 0) * Dn];
        float v1 = vb[(size_t)(k + 1) * Dn];
        float v2 = vb[(size_t)(k + 2) * Dn];
        float v3 = vb[(size_t)(k + 3) * Dn];
        #pragma unroll
        for (int qq = 0; qq < 8; qq++) {
            float4 a = *(const float4*)&s_attn[qq][k];   // broadcast LDS.128
            acc[qq] = fmaf(a.x, v0, acc[qq]);
            acc[qq] = fmaf(a.y, v1, acc[qq]);
            acc[qq] = fmaf(a.z, v2, acc[qq]);
            acc[qq] = fmaf(a.w, v3, acc[qq]);
        }
    }

    #pragma unroll
    for (int qq = 0; qq < 8; qq++) s_part[ks][qq][dl] = acc[qq];
    __syncthreads();

    for (int idx = t; idx < 512; idx += 256) {
        int qq  = idx >> 6;
        int dl2 = idx & 63;
        float s = s_part[0][qq][dl2] + s_part[1][qq][dl2] +
                  s_part[2][qq][dl2] + s_part[3][qq][dl2];
        out[((size_t)(b * Qn + qt * 8 + qq)) * Dn + dc * 64 + dl2] = s;
    }
}

// ============================================================
extern "C" void kernel_launch(void* const* d_in, const int* in_sizes, int n_in,
                              void* d_out, int out_size) {
    const float* queries = (const float*)d_in[0];
    const float* keys    = (const float*)d_in[1];
    const float* values  = (const float*)d_in[2];
    const float* Wq      = (const float*)d_in[3];
    const float* Wk      = (const float*)d_in[4];
    const float* wv      = (const float*)d_in[5];
    const void*  vlens   =               d_in[6];
    float* out = (float*)d_out;

    prep_kernel<<<128, 256>>>(Wq, Wk, wv, vlens);
    proj_kernel<<<(Bn * Qn + Bn * Kn) / 32, 256>>>(queries, keys);
    score_kernel<<<Bn * 16 * 32, 256>>>();
    softmax_kernel<<<Bn * Qn / 2, 256>>>();
    av_kernel<<<Bn * 16 * 4, 256>>>(values, out);
}